// round 7
// baseline (speedup 1.0000x reference)
#include <cuda_runtime.h>

#define N 192
#define NNN (N * N * N)
#define STEPS 20

// Output tile per block
#define TX 32
#define TY 16
#define TZ 16

// c0 staging: tile + 2 halo
#define S0X 36
#define S0Y 20
#define S0Z 20
// c1 staging: tile + 1 halo (x padded to 36 to share indexing; edge cols unused)
#define S1X 36
#define S1Y 18
#define S1Z 18

#define NT 512
#define SMEM_BYTES ((S0X * S0Y * S0Z + S1X * S1Y * S1Z) * (int)sizeof(float))

__device__ float g_scratch[NNN];

__global__ __launch_bounds__(NT) void rd_fused2_kernel(
    const float* __restrict__ src,
    float* __restrict__ dst,
    const float* __restrict__ Dm,
    const float* __restrict__ Rm,
    const float* __restrict__ dt_ptr)
{
    extern __shared__ float sm[];
    float* s0 = sm;                         // c0, [20][20][36]
    float* s1 = sm + S0X * S0Y * S0Z;       // c1, [18][18][36]

    const int tid = threadIdx.x;
    const int ox = blockIdx.x * TX;
    const int oy = blockIdx.y * TY;
    const int oz = blockIdx.z * TZ;

    const float delta_t = dt_ptr[0] * (1.0f / (float)STEPS);

    // ---- stage c0 (zero-filled outside the global domain) ----
    {
        const int warp = tid >> 5, lane = tid & 31;
        for (int r = warp; r < S0Z * S0Y; r += NT / 32) {
            const int z = r / S0Y, y = r - z * S0Y;
            const int gz = oz - 2 + z, gy = oy - 2 + y;
            const bool in_yz = ((unsigned)gz < N) && ((unsigned)gy < N);
            const float* rowp = src + ((size_t)gz * N + gy) * N;
            float* s0row = s0 + r * S0X;
            for (int x = lane; x < S0X; x += 32) {
                const int gx = ox - 2 + x;
                float v = 0.f;
                if (in_yz && (unsigned)gx < N) v = __ldg(rowp + gx);
                s0row[x] = v;
            }
        }
    }
    __syncthreads();

    // ---- step 1: c1 on the 1-halo region, clipped, into s1 ----
    // x columns 0 and 35 produce unused (possibly sloppy) values; step 2 only
    // reads lx in [1,34]. Out-of-domain points get c1 = 0 (zero padding).
    for (int t = tid; t < S1Z * S1Y * S1X; t += NT) {
        const int lx   = t % S1X;
        const int rest = t / S1X;
        const int y1   = rest % S1Y;
        const int z1   = rest / S1Y;

        const int gx = ox - 2 + lx;
        const int gy = oy - 1 + y1;
        const int gz = oz - 1 + z1;

        float c1 = 0.f;
        if (((unsigned)gx < N) && ((unsigned)gy < N) && ((unsigned)gz < N)) {
            const int b = ((z1 + 1) * S0Y + (y1 + 1)) * S0X + lx;
            const float c = s0[b];
            float lap = -6.0f * c;
            lap += (lx > 0)       ? s0[b - 1] : 0.f;   // edge col: unused anyway
            lap += (lx < S1X - 1) ? s0[b + 1] : 0.f;
            lap += s0[b - S0X];
            lap += s0[b + S0X];
            lap += s0[b - S0Y * S0X];
            lap += s0[b + S0Y * S0X];

            const size_t gi = ((size_t)gz * N + gy) * N + gx;
            const float Dv = __ldg(Dm + gi);
            const float Rv = __ldg(Rm + gi);
            c1 = fmaf(fmaf(Dv, lap, Rv * c * (1.0f - c)), delta_t, c);
            c1 = fminf(fmaxf(c1, 0.f), 1.f);
        }
        s1[t] = c1;
    }
    __syncthreads();

    // ---- step 2: c2 on the 32x16x16 interior, write out ----
    for (int t = tid; t < TZ * TY * TX; t += NT) {
        const int x2   = t & (TX - 1);
        const int rest = t / TX;
        const int y2   = rest & (TY - 1);
        const int z2   = rest / TY;

        const int gx = ox + x2, gy = oy + y2, gz = oz + z2;

        const int b = ((z2 + 1) * S1Y + (y2 + 1)) * S1X + (x2 + 2);
        const float c = s1[b];
        float lap = -6.0f * c
                  + s1[b - 1] + s1[b + 1]
                  + s1[b - S1X] + s1[b + S1X]
                  + s1[b - S1Y * S1X] + s1[b + S1Y * S1X];

        const size_t gi = ((size_t)gz * N + gy) * N + gx;
        const float Dv = __ldg(Dm + gi);
        const float Rv = __ldg(Rm + gi);
        float o = fmaf(fmaf(Dv, lap, Rv * c * (1.0f - c)), delta_t, c);
        o = fminf(fmaxf(o, 0.f), 1.f);
        dst[gi] = o;
    }
}

extern "C" void kernel_launch(void* const* d_in, const int* in_sizes, int n_in,
                              void* d_out, int out_size)
{
    const float* c_init = (const float*)d_in[0];
    const float* D_map  = (const float*)d_in[1];
    const float* rho    = (const float*)d_in[2];
    const float* dt     = (const float*)d_in[3];
    float* out = (float*)d_out;

    float* scratch = nullptr;
    cudaGetSymbolAddress((void**)&scratch, g_scratch);

    static bool attr_set = false;
    if (!attr_set) {
        cudaFuncSetAttribute(rd_fused2_kernel,
                             cudaFuncAttributeMaxDynamicSharedMemorySize,
                             SMEM_BYTES);
        attr_set = true;
    }

    dim3 block(NT, 1, 1);
    dim3 grid(N / TX, N / TY, N / TZ);   // (6, 12, 12)

    // 10 fused launches = 20 steps. dst: even -> scratch, odd -> out;
    // launch 9 (last) lands in d_out.
    const float* s = c_init;
    for (int i = 0; i < STEPS / 2; ++i) {
        float* dptr = (i & 1) ? out : scratch;
        rd_fused2_kernel<<<grid, block, SMEM_BYTES>>>(s, dptr, D_map, rho, dt);
        s = dptr;
    }
}

// round 8
// speedup vs baseline: 1.5961x; 1.5961x over previous
#include <cuda_runtime.h>

#define N 192
#define NNN (N * N * N)
#define STEPS 20

#define TX 32          // output tile x (8 float4)
#define TY 16          // output tile y
#define TZ 16          // output tile z (marched)
#define NT 256

#define S0X 40         // c0 row: 10 quads, gx = ox-4 .. ox+35
#define S0Y 20         // c0 rows: gy = oy-2 .. oy+17
#define P0  (S0X * S0Y)   // 800 floats / plane
#define S1X 40         // c1 row (same width; valid x = ox-2..ox+33)
#define S1Y 18         // c1 rows: gy = oy-1 .. oy+16
#define P1  (S1X * S1Y)   // 720 floats / plane

__device__ float g_scratch[NNN];

__device__ __forceinline__ float upd(float c, float xl, float xr,
                                     float ym, float yp, float zm, float zp,
                                     float D, float R, float dt)
{
    float lap = fmaf(-6.f, c, (xl + xr) + (ym + yp) + (zm + zp));
    float u   = fmaf(-c, c, c);                    // c*(1-c)
    return __saturatef(fmaf(dt, fmaf(D, lap, R * u), c));
}

__global__ __launch_bounds__(NT) void rd_fused2(
    const float* __restrict__ src, float* __restrict__ dst,
    const float* __restrict__ Dm, const float* __restrict__ Rm,
    const float* __restrict__ dtp)
{
    __shared__ float s0[4 * P0];   // c0 ring, 4 planes
    __shared__ float s1[4 * P1];   // c1 ring, 4 planes

    const int tid = threadIdx.x;
    const int ox = blockIdx.x * TX;
    const int oy = blockIdx.y * TY;
    const int oz = blockIdx.z * TZ;          // multiple of 16 -> (oz+k)%4 == (k)%4
    const float dt = dtp[0] * (1.0f / (float)STEPS);

    // --- stage c0 plane k (gz = oz+k), zero-filled outside domain ---
    auto stage = [&](int k) {
        const int g = oz + k;
        float* sp = s0 + ((k + 4) & 3) * P0;
        const bool inz = ((unsigned)g < N);
        for (int i = tid; i < S0Y * 10; i += NT) {
            const int row = i / 10;
            const int q   = i - row * 10;
            const int gy  = oy - 2 + row;
            const int gx  = ox - 4 + q * 4;    // quad fully in or out (mult of 4)
            float4 v = make_float4(0.f, 0.f, 0.f, 0.f);
            if (inz && (unsigned)gy < N && (unsigned)gx < N)
                v = __ldg((const float4*)(src + (g * N + gy) * N + gx));
            *(float4*)(sp + row * S0X + q * 4) = v;
        }
    };

    // --- step 1: c1 plane k1 (gz1 = oz+k1), clipped, zero outside domain ---
    auto step1 = [&](int k1) {
        const int g1 = oz + k1;
        float* d1 = s1 + ((k1 + 4) & 3) * P1;
        const float* c0m = s0 + ((k1 - 1 + 4) & 3) * P0;
        const float* c0c = s0 + ((k1     + 4) & 3) * P0;
        const float* c0p = s0 + ((k1 + 1 + 4) & 3) * P0;
        const bool inz = ((unsigned)g1 < N);
        for (int i = tid; i < S1Y * 10; i += NT) {
            const int row = i / 10;
            const int q   = i - row * 10;
            const int gy  = oy - 1 + row;
            const int gx  = ox - 4 + q * 4;
            float4 o = make_float4(0.f, 0.f, 0.f, 0.f);
            if (inz && (unsigned)gy < N && (unsigned)gx < N) {
                const int b = (row + 1) * S0X + q * 4;    // c0 row = c1 row + 1
                const float4 c  = *(const float4*)(c0c + b);
                const float  xl = (q > 0) ? c0c[b - 1] : 0.f;  // edge lanes unread
                const float  xr = (q < 9) ? c0c[b + 4] : 0.f;
                const float4 ym = *(const float4*)(c0c + b - S0X);
                const float4 yp = *(const float4*)(c0c + b + S0X);
                const float4 zm = *(const float4*)(c0m + b);
                const float4 zp = *(const float4*)(c0p + b);
                const int gi = (g1 * N + gy) * N + gx;
                const float4 Dv = __ldg((const float4*)(Dm + gi));
                const float4 Rv = __ldg((const float4*)(Rm + gi));
                o.x = upd(c.x, xl,  c.y, ym.x, yp.x, zm.x, zp.x, Dv.x, Rv.x, dt);
                o.y = upd(c.y, c.x, c.z, ym.y, yp.y, zm.y, zp.y, Dv.y, Rv.y, dt);
                o.z = upd(c.z, c.y, c.w, ym.z, yp.z, zm.z, zp.z, Dv.z, Rv.z, dt);
                o.w = upd(c.w, c.z, xr,  ym.w, yp.w, zm.w, zp.w, Dv.w, Rv.w, dt);
            }
            *(float4*)(d1 + row * S1X + q * 4) = o;
        }
    };

    // --- step 2: c2 output plane z (gz = oz+z), always in-domain ---
    auto step2 = [&](int z) {
        const int gz = oz + z;
        const float* c1m = s1 + ((z - 1 + 4) & 3) * P1;
        const float* c1c = s1 + ((z     + 4) & 3) * P1;
        const float* c1p = s1 + ((z + 1 + 4) & 3) * P1;
        for (int i = tid; i < TY * 8; i += NT) {
            const int row = i >> 3;
            const int q   = i & 7;
            const int gy  = oy + row;
            const int gx  = ox + q * 4;
            const int b = (row + 1) * S1X + (q + 1) * 4;  // c1 row = row+1, quad q+1
            const float4 c  = *(const float4*)(c1c + b);
            const float  xl = c1c[b - 1];
            const float  xr = c1c[b + 4];
            const float4 ym = *(const float4*)(c1c + b - S1X);
            const float4 yp = *(const float4*)(c1c + b + S1X);
            const float4 zm = *(const float4*)(c1m + b);
            const float4 zp = *(const float4*)(c1p + b);
            const int gi = (gz * N + gy) * N + gx;
            const float4 Dv = __ldg((const float4*)(Dm + gi));
            const float4 Rv = __ldg((const float4*)(Rm + gi));
            float4 o;
            o.x = upd(c.x, xl,  c.y, ym.x, yp.x, zm.x, zp.x, Dv.x, Rv.x, dt);
            o.y = upd(c.y, c.x, c.z, ym.y, yp.y, zm.y, zp.y, Dv.y, Rv.y, dt);
            o.z = upd(c.z, c.y, c.w, ym.z, yp.z, zm.z, zp.z, Dv.z, Rv.z, dt);
            o.w = upd(c.w, c.z, xr,  ym.w, yp.w, zm.w, zp.w, Dv.w, Rv.w, dt);
            *(float4*)(dst + gi) = o;
        }
    };

    // ---- prologue ----
    stage(-2); stage(-1); stage(0);
    __syncthreads();
    stage(1); step1(-1); __syncthreads();   // iter z=-3 pattern
    stage(2); step1(0);  __syncthreads();   // iter z=-2
    stage(3); step1(1);  __syncthreads();   // iter z=-1

    // ---- main march: one sync per iteration (rings depth 4 => no intra-iter deps) ----
    for (int z = 0; z < TZ; ++z) {
        if (z <= TZ - 3) stage(z + 4);      // c0 needed up to oz+17
        if (z <= TZ - 2) step1(z + 2);      // c1 needed up to oz+16
        step2(z);
        __syncthreads();
    }
}

extern "C" void kernel_launch(void* const* d_in, const int* in_sizes, int n_in,
                              void* d_out, int out_size)
{
    const float* c_init = (const float*)d_in[0];
    const float* D_map  = (const float*)d_in[1];
    const float* rho    = (const float*)d_in[2];
    const float* dt     = (const float*)d_in[3];
    float* out = (float*)d_out;

    float* scratch = nullptr;
    cudaGetSymbolAddress((void**)&scratch, g_scratch);

    dim3 block(NT, 1, 1);
    dim3 grid(N / TX, N / TY, N / TZ);   // (6, 12, 12) = 864 blocks

    // 10 fused launches = 20 steps; launch 9 (odd) lands in d_out.
    const float* s = c_init;
    for (int i = 0; i < STEPS / 2; ++i) {
        float* dptr = (i & 1) ? out : scratch;
        rd_fused2<<<grid, block>>>(s, dptr, D_map, rho, dt);
        s = dptr;
    }
}

// round 9
// speedup vs baseline: 3.9280x; 2.4609x over previous
#include <cuda_runtime.h>
#include <cuda_fp16.h>

#define N 192
#define NV (N / 4)          // 48 float4 per x-row
#define NNN (N * N * N)
#define STEPS 20

// Ping buffer (pong is d_out). float4 type forces 16B alignment.
__device__ float4 g_scratch4[NNN / 4];
// fp16 maps premultiplied by delta_t, built by prepass each launch.
__device__ __half2 g_Dh2[NNN / 2];
__device__ __half2 g_Rh2[NNN / 2];

// ---- prepass: (D, rho) fp32 -> fp16 * delta_t ----
__global__ __launch_bounds__(256) void convert_maps_kernel(
    const float4* __restrict__ D4, const float4* __restrict__ R4,
    const float* __restrict__ dt_ptr,
    __half2* __restrict__ Dh2, __half2* __restrict__ Rh2)
{
    const int i = blockIdx.x * blockDim.x + threadIdx.x;   // one float4 = 2 half2
    if (i >= NNN / 4) return;
    const float dt = dt_ptr[0] * (1.0f / (float)STEPS);

    const float4 d = D4[i];
    const float4 r = R4[i];
    Dh2[2 * i + 0] = __floats2half2_rn(d.x * dt, d.y * dt);
    Dh2[2 * i + 1] = __floats2half2_rn(d.z * dt, d.w * dt);
    Rh2[2 * i + 0] = __floats2half2_rn(r.x * dt, r.y * dt);
    Rh2[2 * i + 1] = __floats2half2_rn(r.z * dt, r.w * dt);
}

// ---- one time step ----
__global__ __launch_bounds__(192) void rd_step_kernel(
    const float4* __restrict__ src4,
    float4* __restrict__ dst4,
    const __half2* __restrict__ Dh2,
    const __half2* __restrict__ Rh2)
{
    const int tx = threadIdx.x;                            // 0..47 (float4 col)
    const int y  = blockIdx.y * blockDim.y + threadIdx.y;  // 0..191
    const int z  = blockIdx.z;                             // 0..191
    const int idx4 = (z * N + y) * NV + tx;

    const float* src = (const float*)src4;
    const int base = idx4 * 4;

    const float4 zero = make_float4(0.f, 0.f, 0.f, 0.f);

    // Wide loads — issued up-front for MLP.
    const float4 c  = src4[idx4];
    const float4 ym = (y > 0)     ? src4[idx4 - NV]     : zero;
    const float4 yp = (y < N - 1) ? src4[idx4 + NV]     : zero;
    const float4 zm = (z > 0)     ? src4[idx4 - NV * N] : zero;
    const float4 zp = (z < N - 1) ? src4[idx4 + NV * N] : zero;
    // 4 halves of D and R as one 8B load each.
    const uint2 du = *(const uint2*)(Dh2 + 2 * idx4);
    const uint2 ru = *(const uint2*)(Rh2 + 2 * idx4);
    const float left  = (tx > 0)      ? src[base - 1] : 0.f;
    const float right = (tx < NV - 1) ? src[base + 4] : 0.f;

    const float2 d01 = __half22float2(*(const __half2*)&du.x);
    const float2 d23 = __half22float2(*(const __half2*)&du.y);
    const float2 r01 = __half22float2(*(const __half2*)&ru.x);
    const float2 r23 = __half22float2(*(const __half2*)&ru.y);

    // Zero-padded 7-point Laplacian, x-neighbors mostly in-register.
    float4 lap;
    lap.x = left + c.y + ym.x + yp.x + zm.x + zp.x - 6.0f * c.x;
    lap.y = c.x  + c.z + ym.y + yp.y + zm.y + zp.y - 6.0f * c.y;
    lap.z = c.y  + c.w + ym.z + yp.z + zm.z + zp.z - 6.0f * c.z;
    lap.w = c.z  + right + ym.w + yp.w + zm.w + zp.w - 6.0f * c.w;

    // out = c + D'·lap + R'·(c - c²), already scaled by delta_t.
    float4 o;
    o.x = __saturatef(fmaf(d01.x, lap.x, fmaf(r01.x, fmaf(-c.x, c.x, c.x), c.x)));
    o.y = __saturatef(fmaf(d01.y, lap.y, fmaf(r01.y, fmaf(-c.y, c.y, c.y), c.y)));
    o.z = __saturatef(fmaf(d23.x, lap.z, fmaf(r23.x, fmaf(-c.z, c.z, c.z), c.z)));
    o.w = __saturatef(fmaf(d23.y, lap.w, fmaf(r23.y, fmaf(-c.w, c.w, c.w), c.w)));

    dst4[idx4] = o;
}

extern "C" void kernel_launch(void* const* d_in, const int* in_sizes, int n_in,
                              void* d_out, int out_size)
{
    const float4* c_init = (const float4*)d_in[0];
    const float4* D_map  = (const float4*)d_in[1];
    const float4* rho    = (const float4*)d_in[2];
    const float*  dt     = (const float*)d_in[3];
    float4* out = (float4*)d_out;

    float4* scratch = nullptr;
    __half2* Dh2 = nullptr;
    __half2* Rh2 = nullptr;
    cudaGetSymbolAddress((void**)&scratch, g_scratch4);
    cudaGetSymbolAddress((void**)&Dh2, g_Dh2);
    cudaGetSymbolAddress((void**)&Rh2, g_Rh2);

    // Prepass: build fp16 premultiplied maps.
    convert_maps_kernel<<<(NNN / 4 + 255) / 256, 256>>>(D_map, rho, dt, Dh2, Rh2);

    dim3 block(NV, 4, 1);       // 48 x 4 = 192 threads (R2's fastest config)
    dim3 grid(1, N / 4, N);     // (1, 48, 192)

    const float4* src = c_init;
    for (int i = 0; i < STEPS; ++i) {
        float4* dst = (i & 1) ? out : scratch;
        rd_step_kernel<<<grid, block>>>(src, dst, Dh2, Rh2);
        src = dst;
    }
}